// round 3
// baseline (speedup 1.0000x reference)
#include <cuda_runtime.h>
#include <cstdint>

// Problem constants
#define BATCH 8
#define HH 384
#define WW 384
#define PHI 32
#define RHO 64
#define Q_SCALE (255.0f / 32.0f)

// LUT: u[l][c] = ( (relu(l*w1+b1) @ w2 + b2) @ w3 )[c]  * (1/9)
__device__ float g_u[8 * 64];

// ---------------------------------------------------------------------------
// Precompute kernel: one block per level l (8 blocks, 64 threads).
// ---------------------------------------------------------------------------
__global__ void precompute_lut(const float* __restrict__ w1, const float* __restrict__ b1,
                               const float* __restrict__ w2, const float* __restrict__ b2,
                               const float* __restrict__ w3) {
    int l = blockIdx.x;        // level 0..7
    int c = threadIdx.x;       // 0..63
    __shared__ float h2[PHI];

    if (c < PHI) {
        // h2[c] = b2[c] + sum_j relu(l*w1[j] + b1[j]) * w2[j][c]
        float acc = b2[c];
        float lf = (float)l;
#pragma unroll
        for (int j = 0; j < PHI; j++) {
            float h1 = fmaxf(fmaf(lf, w1[j], b1[j]), 0.0f);
            acc = fmaf(h1, w2[j * PHI + c], acc);
        }
        h2[c] = acc;
    }
    __syncthreads();

    float acc = 0.0f;
#pragma unroll
    for (int d = 0; d < PHI; d++) {
        acc = fmaf(h2[d], w3[d * RHO + c], acc);
    }
    g_u[l * RHO + c] = acc * (1.0f / 9.0f);   // fold the mean's 1/9 into the LUT
}

// ---------------------------------------------------------------------------
// Main kernel.
// Tile: TY=8 rows x TX=128 cols per block. Block = (32, 8) = 256 threads.
// Stage A: packed 3x3 nibble-histograms (separable one-hot sums) into SMEM.
// Stage B: thread (q, cg) handles 4 consecutive x (x = x0+4q+i) and
//          8 channels (c = cg*8+k), LUT rows held in registers.
// ---------------------------------------------------------------------------
#define TY 8
#define TX 128

__global__ __launch_bounds__(256, 2)
void lpmp_main(const float* __restrict__ x, const float* __restrict__ b3,
               float* __restrict__ out) {
    const int x0 = blockIdx.x * TX;
    const int y0 = blockIdx.y * TY;
    const int b  = blockIdx.z;

    __shared__ uint32_t rs[TY + 2][TX];   // horizontal 3-sums of one-hot words
    __shared__ uint32_t pk[TY][TX];       // full 3x3 packed counts

    const float* xb = x + (size_t)b * HH * WW;
    const int tid = threadIdx.y * 32 + threadIdx.x;

    // ---- Stage A1: horizontal one-hot 3-sums for rows y0-1 .. y0+TY ----
    for (int idx = tid; idx < (TY + 2) * TX; idx += 256) {
        int r  = idx / TX;
        int xi = idx - r * TX;
        int yg = y0 - 1 + r;
        int xg = x0 + xi;
        uint32_t s;
        if (yg < 0 || yg >= HH) {
            s = 3u;  // three zero-padded pixels, each level 0 -> onehot 1
        } else {
            const float* row = xb + (size_t)yg * WW;
            // center (always in range since x0+xi < WW)
            s = 1u << (4 * (int)(row[xg] * Q_SCALE));
            int xl = xg - 1;
            s += (xl >= 0) ? (1u << (4 * (int)(row[xl] * Q_SCALE))) : 1u;
            int xr = xg + 1;
            s += (xr < WW) ? (1u << (4 * (int)(row[xr] * Q_SCALE))) : 1u;
        }
        rs[r][xi] = s;
    }
    __syncthreads();

    // ---- Stage A2: vertical 3-sums -> packed counts ----
    for (int idx = tid; idx < TY * TX; idx += 256) {
        int r  = idx / TX;
        int xi = idx - r * TX;
        pk[r][xi] = rs[r][xi] + rs[r + 1][xi] + rs[r + 2][xi];
    }

    // ---- Load per-thread LUT slice into registers (independent of SMEM) ----
    const int cg = threadIdx.y;          // channel group 0..7
    const int q  = threadIdx.x;          // x-quad 0..31
    float U[8][8];                        // U[l][k]
    float B3r[8];
#pragma unroll
    for (int l = 0; l < 8; l++)
#pragma unroll
        for (int k = 0; k < 8; k++)
            U[l][k] = g_u[l * RHO + cg * 8 + k];
#pragma unroll
    for (int k = 0; k < 8; k++)
        B3r[k] = b3[cg * 8 + k];

    __syncthreads();

    // ---- Stage B ----
    const int xbase = x0 + 4 * q;
    for (int ty = 0; ty < TY; ty++) {
        float acc[4][8];
#pragma unroll
        for (int i = 0; i < 4; i++) {
            uint32_t p = pk[ty][4 * q + i];
            // counts -> floats without I2F: (bits | 0x4B000000) as float, minus 2^23
            float nf[8];
#pragma unroll
            for (int l = 0; l < 8; l++) {
                uint32_t bits = (p >> (4 * l)) & 0xFu;
                nf[l] = __uint_as_float(bits | 0x4B000000u) - 8388608.0f;
            }
#pragma unroll
            for (int k = 0; k < 8; k++) {
                float a = fmaf(nf[0], U[0][k], B3r[k]);
#pragma unroll
                for (int l = 1; l < 8; l++)
                    a = fmaf(nf[l], U[l][k], a);
                acc[i][k] = fmaxf(a, 0.0f);
            }
        }
        // Vectorized stores: 4 consecutive x per channel
        const int y = y0 + ty;
#pragma unroll
        for (int k = 0; k < 8; k++) {
            const int c = cg * 8 + k;
            float4 v = make_float4(acc[0][k], acc[1][k], acc[2][k], acc[3][k]);
            *reinterpret_cast<float4*>(
                out + ((size_t)(b * RHO + c) * HH + y) * WW + xbase) = v;
        }
    }
}

// ---------------------------------------------------------------------------
// Harness entry point
// ---------------------------------------------------------------------------
extern "C" void kernel_launch(void* const* d_in, const int* in_sizes, int n_in,
                              void* d_out, int out_size) {
    const float* x  = (const float*)d_in[0];
    const float* w1 = (const float*)d_in[1];
    const float* b1 = (const float*)d_in[2];
    const float* w2 = (const float*)d_in[3];
    const float* b2 = (const float*)d_in[4];
    const float* w3 = (const float*)d_in[5];
    const float* b3 = (const float*)d_in[6];
    float* out = (float*)d_out;

    precompute_lut<<<8, 64>>>(w1, b1, w2, b2, w3);

    dim3 grid(WW / TX, HH / TY, BATCH);   // (3, 48, 8)
    dim3 blk(32, 8);
    lpmp_main<<<grid, blk>>>(x, b3, out);
}

// round 4
// speedup vs baseline: 1.2703x; 1.2703x over previous
#include <cuda_runtime.h>
#include <cstdint>

// Problem constants
#define BATCH 8
#define HH 384
#define WW 384
#define PHI 32
#define RHO 64
#define Q_SCALE (255.0f / 32.0f)

#define TY 8
#define TX 128

// ---------------------------------------------------------------------------
// f32x2 packed helpers (sm_103a)
// ---------------------------------------------------------------------------
__device__ __forceinline__ unsigned long long ffma2(unsigned long long a,
                                                    unsigned long long b,
                                                    unsigned long long c) {
    unsigned long long d;
    asm("fma.rn.f32x2 %0, %1, %2, %3;" : "=l"(d) : "l"(a), "l"(b), "l"(c));
    return d;
}
__device__ __forceinline__ unsigned long long pack_dup(float v) {
    unsigned long long d;
    asm("mov.b64 %0, {%1, %1};" : "=l"(d) : "f"(v));
    return d;
}
__device__ __forceinline__ unsigned long long pack2(float lo, float hi) {
    unsigned long long d;
    asm("mov.b64 %0, {%1, %2};" : "=l"(d) : "f"(lo), "f"(hi));
    return d;
}
__device__ __forceinline__ void unpack2(unsigned long long a, float& lo, float& hi) {
    asm("mov.b64 {%0, %1}, %2;" : "=f"(lo), "=f"(hi) : "l"(a));
}

// ---------------------------------------------------------------------------
// Fused kernel: per-block LUT precompute + separable 3x3 histograms + LUT mix.
//
// Math: q = floor(x*255/32) in {0..7}; phi/rho collapse to an 8x64 LUT
//   u[l][c] = (relu(l*w1+b1) @ w2 + b2) @ w3 / 9.
// With per-pixel level counts n_l (Σ n_l = 9, padding = level 0):
//   out[c] = relu( Σ_{l=1..7} n_l * (u[l][c]-u[0][c]) + (b3[c] + 9*u[0][c]) )
// ---------------------------------------------------------------------------
__global__ __launch_bounds__(256, 2)
void lpmp_fused(const float* __restrict__ x,
                const float* __restrict__ w1, const float* __restrict__ b1,
                const float* __restrict__ w2, const float* __restrict__ b2,
                const float* __restrict__ w3, const float* __restrict__ b3,
                float* __restrict__ out) {
    __shared__ float h2S[8][PHI];        // hidden layer per level
    __shared__ float uRaw[8][RHO];       // raw LUT
    __shared__ float uS[7][RHO];         // u[l]-u[0], l=1..7 at index l-1
    __shared__ float biasS[RHO];         // b3 + 9*u[0]
    __shared__ uint32_t rs[TY + 2][TX];  // horizontal one-hot 3-sums
    __shared__ uint32_t pk[TY][TX];      // 3x3 packed nibble counts

    const int x0 = blockIdx.x * TX;
    const int y0 = blockIdx.y * TY;
    const int b  = blockIdx.z;
    const int tid = threadIdx.y * 32 + threadIdx.x;
    const float* xb = x + (size_t)b * HH * WW;

    // ---- Phase 0a: h2[l][d] = b2[d] + sum_j relu(l*w1[j]+b1[j]) * w2[j][d] ----
    {
        int l = tid >> 5;            // 0..7
        int d = tid & 31;            // 0..31
        float acc = b2[d];
        float lf = (float)l;
#pragma unroll
        for (int j = 0; j < PHI; j++) {
            float h1 = fmaxf(fmaf(lf, w1[j], b1[j]), 0.0f);
            acc = fmaf(h1, w2[j * PHI + d], acc);
        }
        h2S[l][d] = acc;
    }
    __syncthreads();

    // ---- Phase 0b: uRaw[l][c] = (h2[l] . w3[:,c]) / 9, 512 entries ----
#pragma unroll
    for (int e = 0; e < 2; e++) {
        int idx = tid + e * 256;
        int l = idx >> 6;            // 0..7
        int c = idx & 63;            // 0..63
        float acc = 0.0f;
#pragma unroll
        for (int d = 0; d < PHI; d++)
            acc = fmaf(h2S[l][d], w3[d * RHO + c], acc);
        uRaw[l][c] = acc * (1.0f / 9.0f);
    }
    __syncthreads();

    // ---- Phase 0c: diff LUT + bias; Stage A1: horizontal one-hot 3-sums ----
    {
        // 448 diff entries + 64 bias entries = 512 -> 2 per thread
#pragma unroll
        for (int e = 0; e < 2; e++) {
            int idx = tid + e * 256;
            if (idx < 448) {
                int l = idx >> 6;        // 0..6 -> level l+1
                int c = idx & 63;
                uS[l][c] = uRaw[l + 1][c] - uRaw[0][c];
            } else {
                int c = idx - 448;
                biasS[c] = fmaf(9.0f, uRaw[0][c], b3[c]);
            }
        }
        // Stage A1: rows y0-1 .. y0+TY, (TY+2)*TX entries
        for (int idx = tid; idx < (TY + 2) * TX; idx += 256) {
            int r  = idx / TX;
            int xi = idx - r * TX;
            int yg = y0 - 1 + r;
            int xg = x0 + xi;
            uint32_t s;
            if (yg < 0 || yg >= HH) {
                s = 3u;  // three zero-padded pixels -> level 0 one-hots
            } else {
                const float* row = xb + (size_t)yg * WW;
                s = 1u << (4 * (int)(row[xg] * Q_SCALE));
                int xl = xg - 1;
                s += (xl >= 0) ? (1u << (4 * (int)(row[xl] * Q_SCALE))) : 1u;
                int xr = xg + 1;
                s += (xr < WW) ? (1u << (4 * (int)(row[xr] * Q_SCALE))) : 1u;
            }
            rs[r][xi] = s;
        }
    }
    __syncthreads();

    // ---- Stage A2: vertical 3-sums -> packed counts ----
    for (int idx = tid; idx < TY * TX; idx += 256) {
        int r  = idx / TX;
        int xi = idx - r * TX;
        pk[r][xi] = rs[r][xi] + rs[r + 1][xi] + rs[r + 2][xi];
    }

    // ---- Load per-thread packed LUT slice (channel pairs) ----
    const int cg = threadIdx.y;   // channel group: channels cg*8 .. cg*8+7
    const int q  = threadIdx.x;   // x-quad: pixels x0+4q .. x0+4q+3
    unsigned long long U2[7][4];  // [level-1][pair]
    unsigned long long B2[4];
#pragma unroll
    for (int p = 0; p < 4; p++) {
        const float2 bv = *reinterpret_cast<const float2*>(&biasS[cg * 8 + 2 * p]);
        B2[p] = pack2(bv.x, bv.y);
    }
    __syncthreads();   // pk ready; uS/biasS reads above are pre-A2-sync safe data
#pragma unroll
    for (int l = 0; l < 7; l++)
#pragma unroll
        for (int p = 0; p < 4; p++) {
            const float2 uv = *reinterpret_cast<const float2*>(&uS[l][cg * 8 + 2 * p]);
            U2[l][p] = pack2(uv.x, uv.y);
        }

    // ---- Stage B: 4 pixels x 8 channels per thread per ty ----
    const int xbase = x0 + 4 * q;
    for (int ty = 0; ty < TY; ty++) {
        float res[4][8];
#pragma unroll
        for (int i = 0; i < 4; i++) {
            const uint32_t p = pk[ty][4 * q + i];
            unsigned long long acc[4];
            // level 1 (index 0) seeds with bias
            {
                uint32_t bits = ((p >> 4) & 0xFu) | 0x4B000000u;
                unsigned long long md = pack_dup(__uint_as_float(bits) - 8388608.0f);
#pragma unroll
                for (int pp = 0; pp < 4; pp++)
                    acc[pp] = ffma2(md, U2[0][pp], B2[pp]);
            }
#pragma unroll
            for (int l = 1; l < 7; l++) {
                uint32_t bits = ((p >> (4 * (l + 1))) & 0xFu) | 0x4B000000u;
                unsigned long long md = pack_dup(__uint_as_float(bits) - 8388608.0f);
#pragma unroll
                for (int pp = 0; pp < 4; pp++)
                    acc[pp] = ffma2(md, U2[l][pp], acc[pp]);
            }
#pragma unroll
            for (int pp = 0; pp < 4; pp++) {
                float lo, hi;
                unpack2(acc[pp], lo, hi);
                res[i][2 * pp]     = fmaxf(lo, 0.0f);
                res[i][2 * pp + 1] = fmaxf(hi, 0.0f);
            }
        }
        // Streaming float4 stores: 4 consecutive x per channel
        const int y = y0 + ty;
#pragma unroll
        for (int k = 0; k < 8; k++) {
            const int c = cg * 8 + k;
            float4 v = make_float4(res[0][k], res[1][k], res[2][k], res[3][k]);
            __stcs(reinterpret_cast<float4*>(
                       out + ((size_t)(b * RHO + c) * HH + y) * WW + xbase), v);
        }
    }
}

// ---------------------------------------------------------------------------
// Harness entry point
// ---------------------------------------------------------------------------
extern "C" void kernel_launch(void* const* d_in, const int* in_sizes, int n_in,
                              void* d_out, int out_size) {
    const float* x  = (const float*)d_in[0];
    const float* w1 = (const float*)d_in[1];
    const float* b1 = (const float*)d_in[2];
    const float* w2 = (const float*)d_in[3];
    const float* b2 = (const float*)d_in[4];
    const float* w3 = (const float*)d_in[5];
    const float* b3 = (const float*)d_in[6];
    float* out = (float*)d_out;

    dim3 grid(WW / TX, HH / TY, BATCH);   // (3, 48, 8)
    dim3 blk(32, 8);
    lpmp_fused<<<grid, blk>>>(x, w1, b1, w2, b2, w3, b3, out);
}